// round 1
// baseline (speedup 1.0000x reference)
#include <cuda_runtime.h>
#include <math.h>

#define HH 512
#define WW 512
#define CC 64
#define HW (HH*WW)
#define TILE 16
#define HALO 2
#define SXD (TILE + 2*HALO)   // 20
#define CI_CHUNK 16
#define CO_BLK 16

__device__ float g_xori[CC * HW];          // 64 MB scratch
__device__ unsigned char g_md[HW];

__device__ __forceinline__ int reflect512(int i) {
    if (i < 0) i = -i;
    if (i >= 512) i = 1022 - i;
    return i;
}

__device__ __forceinline__ float gelu_exact(float v) {
    return 0.5f * v * (1.0f + erff(v * 0.70710678118654752f));
}

__global__ void md_kernel(const float* __restrict__ mask) {
    int x = blockIdx.x * 32 + threadIdx.x;
    int y = blockIdx.y * 8 + threadIdx.y;
    float m = 0.0f;
    #pragma unroll
    for (int dy = -2; dy <= 2; dy++) {
        int yy = y + dy;
        if (yy < 0 || yy >= HH) continue;
        #pragma unroll
        for (int dx = -2; dx <= 2; dx++) {
            int xx = x + dx;
            if (xx < 0 || xx >= WW) continue;
            m = fmaxf(m, mask[yy * WW + xx]);
        }
    }
    g_md[y * WW + x] = (m > 0.5f) ? 1 : 0;
}

// MODE 1: in = x           -> g_xori = md ? gelu(conv+b1) : x
// MODE 2: in = g_xori      -> d_out[sd] = gelu(conv+b2) + x
template <int MODE>
__global__ void __launch_bounds__(256) conv_kernel(
    const float* __restrict__ xres,   // original x (epilogue + MODE1 input)
    const float* __restrict__ wgt,    // (64,64,3,3) OIHW
    const float* __restrict__ bias,   // (64,)
    const float* __restrict__ mask,   // (H,W)
    float* __restrict__ out)          // d_out (MODE2)
{
    __shared__ float sx[CI_CHUNK][SXD][SXD];
    __shared__ float sw[CI_CHUNK * 9 * CO_BLK];

    const float* in = (MODE == 1) ? xres : (const float*)g_xori;

    const int tid = threadIdx.x;
    const int lx = tid & 15;
    const int ly = tid >> 4;
    const int bx = blockIdx.x * TILE;
    const int by = blockIdx.y * TILE;
    const int co0 = blockIdx.z * CO_BLK;

    float acc[CO_BLK];
    #pragma unroll
    for (int i = 0; i < CO_BLK; i++) acc[i] = 0.0f;

    for (int cc = 0; cc < CC; cc += CI_CHUNK) {
        for (int idx = tid; idx < CI_CHUNK * SXD * SXD; idx += 256) {
            int ci  = idx / (SXD * SXD);
            int rem = idx - ci * (SXD * SXD);
            int r   = rem / SXD;
            int c2  = rem - r * SXD;
            int gy = reflect512(by - HALO + r);
            int gx = reflect512(bx - HALO + c2);
            sx[ci][r][c2] = in[(cc + ci) * HW + gy * WW + gx];
        }
        for (int idx = tid; idx < CI_CHUNK * 9 * CO_BLK; idx += 256) {
            int col  = idx & 15;
            int rest = idx >> 4;       // ci*9 + k
            int ci   = rest / 9;
            int k    = rest - ci * 9;
            sw[idx] = wgt[(co0 + col) * (CC * 9) + (cc + ci) * 9 + k];
        }
        __syncthreads();

        #pragma unroll 4
        for (int ci = 0; ci < CI_CHUNK; ci++) {
            #pragma unroll
            for (int k = 0; k < 9; k++) {
                const int dy = (k / 3) * 2;
                const int dx = (k % 3) * 2;
                float xv = sx[ci][ly + dy][lx + dx];
                const float4* wv = reinterpret_cast<const float4*>(&sw[(ci * 9 + k) * CO_BLK]);
                float4 w0 = wv[0], w1 = wv[1], w2 = wv[2], w3 = wv[3];
                acc[0]  = fmaf(xv, w0.x, acc[0]);
                acc[1]  = fmaf(xv, w0.y, acc[1]);
                acc[2]  = fmaf(xv, w0.z, acc[2]);
                acc[3]  = fmaf(xv, w0.w, acc[3]);
                acc[4]  = fmaf(xv, w1.x, acc[4]);
                acc[5]  = fmaf(xv, w1.y, acc[5]);
                acc[6]  = fmaf(xv, w1.z, acc[6]);
                acc[7]  = fmaf(xv, w1.w, acc[7]);
                acc[8]  = fmaf(xv, w2.x, acc[8]);
                acc[9]  = fmaf(xv, w2.y, acc[9]);
                acc[10] = fmaf(xv, w2.z, acc[10]);
                acc[11] = fmaf(xv, w2.w, acc[11]);
                acc[12] = fmaf(xv, w3.x, acc[12]);
                acc[13] = fmaf(xv, w3.y, acc[13]);
                acc[14] = fmaf(xv, w3.z, acc[14]);
                acc[15] = fmaf(xv, w3.w, acc[15]);
            }
        }
        __syncthreads();
    }

    const int gy = by + ly;
    const int gx = bx + lx;
    const int p = gy * WW + gx;

    if (MODE == 1) {
        const bool md = (g_md[p] != 0);
        #pragma unroll
        for (int co = 0; co < CO_BLK; co++) {
            float v = gelu_exact(acc[co] + bias[co0 + co]);
            int o = (co0 + co) * HW + p;
            g_xori[o] = md ? v : xres[o];
        }
    } else {
        if (mask[p] > 0.5f) {
            #pragma unroll
            for (int co = 0; co < CO_BLK; co++) {
                float v = gelu_exact(acc[co] + bias[co0 + co]);
                int o = (co0 + co) * HW + p;
                out[o] = v + xres[o];
            }
        }
    }
}

__global__ void dw_kernel(
    const float* __restrict__ x,
    const float* __restrict__ w3,
    const float* __restrict__ b3,
    const float* __restrict__ mask,
    float* __restrict__ out)
{
    int gx = blockIdx.x * 256 + threadIdx.x;
    int gy = blockIdx.y;
    int c  = blockIdx.z;
    int p  = gy * WW + gx;
    if (mask[p] > 0.5f) return;

    const float* wc = w3 + c * 9;
    const float* xc = x + c * HW;
    float a = 0.0f;
    #pragma unroll
    for (int k = 0; k < 9; k++) {
        int yy = reflect512(gy + (k / 3) * 2 - 2);
        int xx = reflect512(gx + (k % 3) * 2 - 2);
        a = fmaf(xc[yy * WW + xx], wc[k], a);
    }
    out[c * HW + p] = gelu_exact(a + b3[c]) + xc[p];
}

extern "C" void kernel_launch(void* const* d_in, const int* in_sizes, int n_in,
                              void* d_out, int out_size) {
    const float* x    = (const float*)d_in[0];
    const float* mask = (const float*)d_in[1];
    const float* w1   = (const float*)d_in[2];
    const float* b1   = (const float*)d_in[3];
    const float* w2   = (const float*)d_in[4];
    const float* b2   = (const float*)d_in[5];
    const float* w3   = (const float*)d_in[6];
    const float* b3   = (const float*)d_in[7];
    float* out = (float*)d_out;

    md_kernel<<<dim3(WW / 32, HH / 8), dim3(32, 8)>>>(mask);

    dim3 cgrid(WW / TILE, HH / TILE, CC / CO_BLK);
    conv_kernel<1><<<cgrid, 256>>>(x, w1, b1, mask, out);

    dw_kernel<<<dim3(WW / 256, HH, CC), 256>>>(x, w3, b3, mask, out);

    conv_kernel<2><<<cgrid, 256>>>(x, w2, b2, mask, out);
}

// round 2
// speedup vs baseline: 1.3492x; 1.3492x over previous
#include <cuda_runtime.h>
#include <math.h>

#define HH 512
#define WW 512
#define CC 64
#define HW (HH*WW)
#define TILE 32              // spatial tile (32x32), 4 px per thread
#define HALO 2
#define SXD (TILE + 2*HALO)  // 36
#define SXP 37               // padded row stride (bank-conflict-free)
#define CI_CHUNK 8
#define CO_BLK 16

typedef unsigned long long ull;

__device__ float g_xori[CC * HW];          // 64 MB scratch
__device__ unsigned char g_md[HW];

__device__ __forceinline__ int reflect512(int i) {
    if (i < 0) i = -i;
    if (i >= 512) i = 1022 - i;
    return i;
}

__device__ __forceinline__ float gelu_exact(float v) {
    return 0.5f * v * (1.0f + erff(v * 0.70710678118654752f));
}

// packed fp32x2 helpers (sm_100+)
__device__ __forceinline__ ull splat2(float x) {
    ull r;
    asm("mov.b64 %0, {%1, %1};" : "=l"(r) : "f"(x));
    return r;
}
__device__ __forceinline__ void ffma2(ull& a, ull x, ull w) {
    asm("fma.rn.f32x2 %0, %1, %2, %0;" : "+l"(a) : "l"(x), "l"(w));
}
__device__ __forceinline__ float2 unpack2(ull a) {
    float2 f;
    asm("mov.b64 {%0, %1}, %2;" : "=f"(f.x), "=f"(f.y) : "l"(a));
    return f;
}

// ---------------------------------------------------------------------------
__global__ void md_kernel(const float* __restrict__ mask) {
    int x = blockIdx.x * 32 + threadIdx.x;
    int y = blockIdx.y * 8 + threadIdx.y;
    float m = 0.0f;
    #pragma unroll
    for (int dy = -2; dy <= 2; dy++) {
        int yy = y + dy;
        if (yy < 0 || yy >= HH) continue;
        #pragma unroll
        for (int dx = -2; dx <= 2; dx++) {
            int xx = x + dx;
            if (xx < 0 || xx >= WW) continue;
            m = fmaxf(m, mask[yy * WW + xx]);
        }
    }
    g_md[y * WW + x] = (m > 0.5f) ? 1 : 0;
}

// ---------------------------------------------------------------------------
// MODE 1: in = x       -> g_xori = md ? gelu(conv+b1) : x
// MODE 2: in = g_xori  -> d_out[sd] = gelu(conv+b2) + x
// 32x32 spatial tile, 16 output channels per block, 4 pixels per thread,
// co-dimension packed in f32x2 (8 packed accumulator pairs per pixel).
// ---------------------------------------------------------------------------
template <int MODE>
__global__ void __launch_bounds__(256, 2) conv_kernel(
    const float* __restrict__ xres,   // original x
    const float* __restrict__ wgt,    // (64,64,3,3) OIHW
    const float* __restrict__ bias,   // (64,)
    const float* __restrict__ mask,   // (H,W)
    float* __restrict__ out)
{
    __shared__ __align__(16) float sx[CI_CHUNK][SXD][SXP];   // 42.6 KB
    __shared__ __align__(16) float sw[CI_CHUNK * 9 * CO_BLK]; // 4.6 KB

    const float* in = (MODE == 1) ? xres : (const float*)g_xori;

    const int tid = threadIdx.x;
    const int lx = tid & 15;         // 0..15 -> pixel columns 2lx, 2lx+1
    const int ly = tid >> 4;         // 0..15 -> pixel rows ly, ly+16
    const int bx = blockIdx.x * TILE;
    const int by = blockIdx.y * TILE;
    const int co0 = blockIdx.z * CO_BLK;

    ull acc[4][8];
    #pragma unroll
    for (int p = 0; p < 4; p++)
        #pragma unroll
        for (int i = 0; i < 8; i++) acc[p][i] = 0ull;

    for (int cc = 0; cc < CC; cc += CI_CHUNK) {
        // stage input tile (reflect-padded halo), padded stride SXP
        for (int idx = tid; idx < CI_CHUNK * SXD * SXP; idx += 256) {
            int ci  = idx / (SXD * SXP);
            int rem = idx - ci * (SXD * SXP);
            int r   = rem / SXP;
            int c2  = rem - r * SXP;
            int gy = reflect512(by - HALO + r);
            int gx = reflect512(bx - HALO + c2);
            sx[ci][r][c2] = in[(cc + ci) * HW + gy * WW + gx];
        }
        // stage weights: sw[(ci*9+k)*16 + co_local] (co pairs contiguous)
        for (int idx = tid; idx < CI_CHUNK * 9 * CO_BLK; idx += 256) {
            int col  = idx & 15;
            int rest = idx >> 4;       // ci*9 + k
            int ci   = rest / 9;
            int k    = rest - ci * 9;
            sw[idx] = wgt[(co0 + col) * (CC * 9) + (cc + ci) * 9 + k];
        }
        __syncthreads();

        for (int ci = 0; ci < CI_CHUNK; ci++) {
            #pragma unroll
            for (int k = 0; k < 9; k++) {
                const int dy = (k / 3) * 2;
                const int dx = (k % 3) * 2;
                const ulonglong2* wp =
                    reinterpret_cast<const ulonglong2*>(&sw[(ci * 9 + k) * CO_BLK]);
                ulonglong2 wa = wp[0];   // co pairs 0-1, 2-3
                ulonglong2 wb = wp[1];   // co pairs 4-5, 6-7
                #pragma unroll
                for (int pr = 0; pr < 2; pr++) {
                    #pragma unroll
                    for (int px = 0; px < 2; px++) {
                        float xv = sx[ci][ly + 16 * pr + dy][2 * lx + px + dx];
                        ull x2 = splat2(xv);
                        ull* a = acc[pr * 2 + px];
                        ffma2(a[0], x2, wa.x);
                        ffma2(a[1], x2, wa.y);
                        ffma2(a[2], x2, wb.x);
                        ffma2(a[3], x2, wb.y);
                        const ulonglong2 wc = wp[2];
                        const ulonglong2 wd = wp[3];
                        ffma2(a[4], x2, wc.x);
                        ffma2(a[5], x2, wc.y);
                        ffma2(a[6], x2, wd.x);
                        ffma2(a[7], x2, wd.y);
                    }
                }
            }
        }
        __syncthreads();
    }

    // epilogue: 4 pixels x 16 channels
    #pragma unroll
    for (int pr = 0; pr < 2; pr++) {
        #pragma unroll
        for (int px = 0; px < 2; px++) {
            const int gy = by + ly + 16 * pr;
            const int gx = bx + 2 * lx + px;
            const int p = gy * WW + gx;
            const ull* a = acc[pr * 2 + px];

            if (MODE == 1) {
                const bool md = (g_md[p] != 0);
                #pragma unroll
                for (int j = 0; j < 8; j++) {
                    float2 v = unpack2(a[j]);
                    int c0 = co0 + 2 * j;
                    float r0 = gelu_exact(v.x + bias[c0]);
                    float r1 = gelu_exact(v.y + bias[c0 + 1]);
                    g_xori[c0 * HW + p]       = md ? r0 : xres[c0 * HW + p];
                    g_xori[(c0 + 1) * HW + p] = md ? r1 : xres[(c0 + 1) * HW + p];
                }
            } else {
                if (mask[p] > 0.5f) {
                    #pragma unroll
                    for (int j = 0; j < 8; j++) {
                        float2 v = unpack2(a[j]);
                        int c0 = co0 + 2 * j;
                        out[c0 * HW + p]       = gelu_exact(v.x + bias[c0]) + xres[c0 * HW + p];
                        out[(c0 + 1) * HW + p] = gelu_exact(v.y + bias[c0 + 1]) + xres[(c0 + 1) * HW + p];
                    }
                }
            }
        }
    }
}

// ---------------------------------------------------------------------------
__global__ void dw_kernel(
    const float* __restrict__ x,
    const float* __restrict__ w3,
    const float* __restrict__ b3,
    const float* __restrict__ mask,
    float* __restrict__ out)
{
    int gx = blockIdx.x * 256 + threadIdx.x;
    int gy = blockIdx.y;
    int c  = blockIdx.z;
    int p  = gy * WW + gx;
    if (mask[p] > 0.5f) return;

    const float* wc = w3 + c * 9;
    const float* xc = x + c * HW;
    float a = 0.0f;
    #pragma unroll
    for (int k = 0; k < 9; k++) {
        int yy = reflect512(gy + (k / 3) * 2 - 2);
        int xx = reflect512(gx + (k % 3) * 2 - 2);
        a = fmaf(xc[yy * WW + xx], wc[k], a);
    }
    out[c * HW + p] = gelu_exact(a + b3[c]) + xc[p];
}

// ---------------------------------------------------------------------------
extern "C" void kernel_launch(void* const* d_in, const int* in_sizes, int n_in,
                              void* d_out, int out_size) {
    const float* x    = (const float*)d_in[0];
    const float* mask = (const float*)d_in[1];
    const float* w1   = (const float*)d_in[2];
    const float* b1   = (const float*)d_in[3];
    const float* w2   = (const float*)d_in[4];
    const float* b2   = (const float*)d_in[5];
    const float* w3   = (const float*)d_in[6];
    const float* b3   = (const float*)d_in[7];
    float* out = (float*)d_out;

    md_kernel<<<dim3(WW / 32, HH / 8), dim3(32, 8)>>>(mask);

    dim3 cgrid(WW / TILE, HH / TILE, CC / CO_BLK);   // 16 x 16 x 4 = 1024 blocks
    conv_kernel<1><<<cgrid, 256>>>(x, w1, b1, mask, out);

    dw_kernel<<<dim3(WW / 256, HH, CC), 256>>>(x, w3, b3, mask, out);

    conv_kernel<2><<<cgrid, 256>>>(x, w2, b2, mask, out);
}